// round 16
// baseline (speedup 1.0000x reference)
#include <cuda_runtime.h>
#include <cuda_bf16.h>
#include <math.h>
#include <string.h>
#include <stdint.h>

#define BB 4
#define SS 2048
#define VV 64
#define DD 1024
#define PP 8
#define HH 42
#define KK 49152
#define EPSF 1e-12f
#define COSEPS 1e-8f
#define SQRT_S 45.254834f   // sqrt(2048)

typedef unsigned long long ull;

// ---------------- scratch (static device globals; no allocs allowed) ----------------
__device__ float g_w1t[HH * DD];              // w1 transposed [H][D]
__device__ float g_n[PP * BB * SS];           // n values
__device__ float g_wsm[PP * BB * SS];         // softmax weights over s
__device__ float4 g_cred[PP * BB * 32];       // cos partials {dot, an2, en2, 0} per (pb, dchunk)
__device__ float g_htab[PP * VV * HH];        // tanh(tables@w1+b1) [512][42]

// ---------------- kernel 1: knorm — n[p,b,s]; tail: w1 transpose ----------------
__global__ __launch_bounds__(256) void knorm(const float* __restrict__ ctx,
                                             const float* __restrict__ lora,
                                             const float* __restrict__ w1) {
    __shared__ float su[PP * DD];
    int t = threadIdx.x, warp = t >> 5, lane = t & 31;
    for (int i = t; i < PP * DD; i += 256) {
        float e = lora[i];
        su[i] = e / fmaxf(2.0f * fabsf(e), EPSF);
    }
    __syncthreads();
    int row = blockIdx.x * 8 + warp;
    int b = row >> 11, s = row & 2047;
    const float4* x4 = reinterpret_cast<const float4*>(ctx + (size_t)row * DD);
    float nrm2 = 0.f;
    float dot[PP];
#pragma unroll
    for (int p = 0; p < PP; p++) dot[p] = 0.f;
#pragma unroll
    for (int it = 0; it < 8; it++) {
        int q = lane + it * 32;
        float4 x = x4[q];
        nrm2 += x.x * x.x + x.y * x.y + x.z * x.z + x.w * x.w;
#pragma unroll
        for (int p = 0; p < PP; p++) {
            float4 u = reinterpret_cast<const float4*>(su + p * DD)[q];
            dot[p] += x.x * u.x + x.y * u.y + x.z * u.z + x.w * u.w;
        }
    }
#pragma unroll
    for (int o = 16; o; o >>= 1) {
        nrm2 += __shfl_xor_sync(0xffffffffu, nrm2, o);
#pragma unroll
        for (int p = 0; p < PP; p++) dot[p] += __shfl_xor_sync(0xffffffffu, dot[p], o);
    }
    if (lane < PP) {
        float dl = 0.f;
#pragma unroll
        for (int p = 0; p < PP; p++) if (lane == p) dl = dot[p];
        float v = dl / fmaxf(sqrtf(nrm2), EPSF);
        float c = fmaxf(v, 0.f);
        g_n[((size_t)lane * BB + b) * SS + s] = c / fmaxf(SQRT_S * c, EPSF);
    }
    if (blockIdx.x < 168) {
        int idx = blockIdx.x * 256 + t;
        int d = idx / HH, h = idx - d * HH;
        g_w1t[(size_t)h * DD + d] = w1[idx];
    }
}

// ---------------- kernel 2: ksofth — softmax (blk<32) || htab 8 rows (32<=blk<96) ----
__global__ __launch_bounds__(256) void ksofth(const float* __restrict__ tables,
                                              const float* __restrict__ b1) {
    __shared__ float smem[8 * DD];
    int blk = blockIdx.x;
    int t = threadIdx.x, warp = t >> 5, lane = t & 31;
    if (blk < 32) {
        float* sn = smem;
        float* red = smem + SS;
        int pb = blk;
        const float* np = g_n + (size_t)pb * SS;
        float m = -1e30f;
        for (int i = t; i < SS; i += 256) { float v = np[i]; sn[i] = v; m = fmaxf(m, v); }
        red[t] = m; __syncthreads();
        for (int o = 128; o; o >>= 1) { if (t < o) red[t] = fmaxf(red[t], red[t + o]); __syncthreads(); }
        m = red[0]; __syncthreads();
        float sum = 0.f;
        for (int i = t; i < SS; i += 256) sum += expf(sn[i] - m);
        red[t] = sum; __syncthreads();
        for (int o = 128; o; o >>= 1) { if (t < o) red[t] += red[t + o]; __syncthreads(); }
        float inv = 1.0f / red[0];
        for (int i = t; i < SS; i += 256) g_wsm[(size_t)pb * SS + i] = expf(sn[i] - m) * inv;
    } else {
        float* tok = smem;
        int oct = blk - 32;
        const float* src = tables + (size_t)oct * 8 * DD;
        for (int i = t; i < 8 * DD; i += 256) tok[i] = src[i];
        __syncthreads();
#pragma unroll
        for (int j = 0; j < 6; j++) {
            int h = warp + j * 8;
            if (h < HH) {
                const float4* wr = reinterpret_cast<const float4*>(g_w1t + (size_t)h * DD);
                float dt[8];
#pragma unroll
                for (int r = 0; r < 8; r++) dt[r] = 0.f;
#pragma unroll
                for (int it = 0; it < 8; it++) {
                    int q = lane + it * 32;
                    float4 wv = wr[q];
#pragma unroll
                    for (int r = 0; r < 8; r++) {
                        float4 tv = reinterpret_cast<const float4*>(tok + r * DD)[q];
                        dt[r] += wv.x * tv.x + wv.y * tv.y + wv.z * tv.z + wv.w * tv.w;
                    }
                }
#pragma unroll
                for (int o = 16; o; o >>= 1)
#pragma unroll
                    for (int r = 0; r < 8; r++) dt[r] += __shfl_xor_sync(0xffffffffu, dt[r], o);
                if (lane < 8) {
                    float dl = 0.f;
#pragma unroll
                    for (int r = 0; r < 8; r++) if (lane == r) dl = dt[r];
                    g_htab[(size_t)(oct * 8 + lane) * HH + h] = tanhf(dl + b1[h]);
                }
            }
        }
    }
}

// ---------------- kernel 3: kavd — direct a_v + cos partials ----------------
__global__ __launch_bounds__(1024) void kavd(const float* __restrict__ ctx,
                                             const float* __restrict__ lora) {
    extern __shared__ float dsm[];
    float* ws = dsm;
    float* red = dsm + PP * SS;
    int b = blockIdx.x & 3, dchunk = blockIdx.x >> 2;
    int t = threadIdx.x, w = t >> 5, lane = t & 31;
    for (int i = t; i < PP * SS; i += 1024) {
        int p = i >> 11, s = i & 2047;
        ws[i] = g_wsm[((size_t)p * BB + b) * SS + s];
    }
    __syncthreads();
    int d = dchunk * 32 + lane;
    const float* cb = ctx + (size_t)b * SS * DD + d;
    int s0 = w * 64;
    float acc[PP];
#pragma unroll
    for (int p = 0; p < PP; p++) acc[p] = 0.f;
#pragma unroll
    for (int sb = 0; sb < 64; sb += 16) {
        float x[16];
#pragma unroll
        for (int r = 0; r < 16; r++) x[r] = cb[(size_t)(s0 + sb + r) * DD];
#pragma unroll
        for (int r = 0; r < 16; r++) {
            int s = s0 + sb + r;
            float xs = x[r];
#pragma unroll
            for (int p = 0; p < PP; p++) acc[p] += ws[p * SS + s] * xs;
        }
    }
#pragma unroll
    for (int p = 0; p < PP; p++) red[(w * PP + p) * 32 + lane] = acc[p];
    __syncthreads();
    if (w < PP) {
        int p = w;
        float av = 0.f;
#pragma unroll
        for (int ww = 0; ww < 32; ww++) av += red[(ww * PP + p) * 32 + lane];
        float e = lora[(size_t)p * DD + d];
        float dotv = e * av, an2 = av * av, en2 = e * e;
#pragma unroll
        for (int o = 16; o; o >>= 1) {
            dotv += __shfl_xor_sync(0xffffffffu, dotv, o);
            an2  += __shfl_xor_sync(0xffffffffu, an2, o);
            en2  += __shfl_xor_sync(0xffffffffu, en2, o);
        }
        if (lane == 0)
            g_cred[(p * BB + b) * 32 + dchunk] = make_float4(dotv, an2, en2, 0.f);
    }
}

// ---------------- kernel 4: kout — split-bf16 HMMA GEMM ----------------
// out[256,49152] = hbar[256,42] @ w2 + b2 with A' = [Ah|Ah|Al] (K=144),
// B' = [Wh;Wl;Wh] so one MMA chain = AhWh + AhWl + AlWh (err ~2^-18).
// Block: 256 thr = 8 warps (4 m16 x 2 n64). Tile M=64 x N=128. grid (384,4).

#define KSEG 48                 // padded K per segment (42 -> 48)
#define KT 144                  // 3 segments
#define AST2 152                // A smem row stride (bf16) -> 304B, 16B-mult, conflict-free
#define BST2 136                // B smem row stride (bf16) -> 272B, 16B-mult, conflict-free

__device__ __forceinline__ uint32_t smem_u32(const void* p) {
    return (uint32_t)__cvta_generic_to_shared(p);
}

#define LDSM_X4(r0,r1,r2,r3,addr) \
    asm volatile("ldmatrix.sync.aligned.m8n8.x4.shared.b16 {%0,%1,%2,%3}, [%4];" \
        : "=r"(r0), "=r"(r1), "=r"(r2), "=r"(r3) : "r"(addr))

#define LDSM_X4T(r0,r1,r2,r3,addr) \
    asm volatile("ldmatrix.sync.aligned.m8n8.x4.trans.shared.b16 {%0,%1,%2,%3}, [%4];" \
        : "=r"(r0), "=r"(r1), "=r"(r2), "=r"(r3) : "r"(addr))

#define MMA_BF16(d, a0,a1,a2,a3, b0,b1) \
    asm volatile("mma.sync.aligned.m16n8k16.row.col.f32.bf16.bf16.f32 " \
        "{%0,%1,%2,%3}, {%4,%5,%6,%7}, {%8,%9}, {%0,%1,%2,%3};" \
        : "+f"(d[0]), "+f"(d[1]), "+f"(d[2]), "+f"(d[3]) \
        : "r"(a0), "r"(a1), "r"(a2), "r"(a3), "r"(b0), "r"(b1))

__global__ __launch_bounds__(256) void kout(const int* __restrict__ prefix,
                                            const float* __restrict__ w2,
                                            const float* __restrict__ b2,
                                            float* __restrict__ out) {
    extern __shared__ __nv_bfloat16 bsm[];
    __nv_bfloat16* s_a = bsm;                   // [64][AST2]
    __nv_bfloat16* s_b = bsm + 64 * AST2;       // [KT][BST2]
    __shared__ float scos[32];
    __shared__ float sgate[32];

    int t = threadIdx.x;
    int r0g = blockIdx.y * 64;
    int col0 = blockIdx.x * 128;

    // ---- gates (t<32) ----
    if (t < 32) {
        float D = 0.f, A = 0.f, E = 0.f;
#pragma unroll 8
        for (int c = 0; c < 32; c++) {
            float4 f = g_cred[t * 32 + c];
            D += f.x; A += f.y; E += f.z;
        }
        scos[t] = D / fmaxf(sqrtf(E) * sqrtf(A), COSEPS);
        __syncwarp();
        int bq = t >> 3, p = t & 7;
        float x[PP], m = -1e30f;
#pragma unroll
        for (int pp = 0; pp < PP; pp++) { x[pp] = scos[pp * BB + bq]; m = fmaxf(m, x[pp]); }
        float z = 0.f;
#pragma unroll
        for (int pp = 0; pp < PP; pp++) { x[pp] = expf(x[pp] - m); z += x[pp]; }
#pragma unroll
        for (int pp = 0; pp < PP; pp++) x[pp] /= z;
        m = -1e30f;
#pragma unroll
        for (int pp = 0; pp < PP; pp++) m = fmaxf(m, x[pp]);
        z = 0.f;
#pragma unroll
        for (int pp = 0; pp < PP; pp++) { x[pp] = expf(x[pp] - m); z += x[pp]; }
        sgate[t] = x[p] / z;
    }
    __syncthreads();

    // ---- stage A' = [Ah | Ah | Al] per row (hbar gather + split) ----
    for (int i = t; i < 64 * KSEG; i += 256) {
        int r = i / KSEG, h = i - r * KSEG;
        float v = 0.f;
        if (h < HH) {
            int bv = r0g + r;
            int pf = prefix[bv];
            int bq = bv >> 6;
            float s = 0.f;
#pragma unroll
            for (int p = 0; p < PP; p++)
                s += sgate[bq * 8 + p] * g_htab[((size_t)p * VV + pf) * HH + h];
            v = s;
        }
        __nv_bfloat16 ah = __float2bfloat16(v);
        __nv_bfloat16 al = __float2bfloat16(v - __bfloat162float(ah));
        s_a[r * AST2 + h]            = ah;
        s_a[r * AST2 + KSEG + h]     = ah;
        s_a[r * AST2 + 2 * KSEG + h] = al;
    }
    // ---- stage B' = [Wh ; Wl ; Wh] ----
    for (int i = t; i < KSEG * 128; i += 256) {
        int k = i >> 7, n = i & 127;
        float v = (k < HH) ? w2[(size_t)k * KK + col0 + n] : 0.f;
        __nv_bfloat16 wh = __float2bfloat16(v);
        __nv_bfloat16 wl = __float2bfloat16(v - __bfloat162float(wh));
        s_b[k * BST2 + n]                = wh;
        s_b[(KSEG + k) * BST2 + n]       = wl;
        s_b[(2 * KSEG + k) * BST2 + n]   = wh;
    }
    __syncthreads();

    // ---- MMA mainloop: 9 k16 chunks ----
    int w = t >> 5, lane = t & 31;
    int mi = w & 3, ni = w >> 2;               // 4 m16 tiles x 2 n64 halves
    int lmat = lane >> 3, lrow = lane & 7;

    uint32_t a_base = smem_u32(s_a) +
        (((mi * 16 + (lmat & 1) * 8 + lrow) * AST2) + (lmat >> 1) * 8) * 2;
    uint32_t b_base = smem_u32(s_b) +
        ((((lmat & 1) * 8 + lrow) * BST2) + ni * 64 + (lmat >> 1) * 8) * 2;

    float acc[8][4];
#pragma unroll
    for (int j = 0; j < 8; j++)
#pragma unroll
        for (int q = 0; q < 4; q++) acc[j][q] = 0.f;

#pragma unroll
    for (int kc = 0; kc < 9; kc++) {
        uint32_t a0, a1, a2, a3;
        LDSM_X4(a0, a1, a2, a3, a_base + kc * 16 * 2);
#pragma unroll
        for (int j = 0; j < 4; j++) {
            uint32_t b0, b1, b2v, b3;
            LDSM_X4T(b0, b1, b2v, b3, b_base + (kc * 16 * BST2 + j * 16) * 2);
            MMA_BF16(acc[2 * j],     a0, a1, a2, a3, b0, b1);
            MMA_BF16(acc[2 * j + 1], a0, a1, a2, a3, b2v, b3);
        }
    }

    // ---- store with bias ----
    int row = r0g + mi * 16 + (lane >> 2);
#pragma unroll
    for (int j = 0; j < 8; j++) {
        int col = col0 + ni * 64 + j * 8 + (lane & 3) * 2;
        float2 bb = *reinterpret_cast<const float2*>(b2 + col);
        float2 o0 = make_float2(acc[j][0] + bb.x, acc[j][1] + bb.y);
        float2 o1 = make_float2(acc[j][2] + bb.x, acc[j][3] + bb.y);
        *reinterpret_cast<float2*>(out + (size_t)row * KK + col) = o0;
        *reinterpret_cast<float2*>(out + (size_t)(row + 8) * KK + col) = o1;
    }
}

// ---------------- launcher ----------------
extern "C" void kernel_launch(void* const* d_in, const int* in_sizes, int n_in,
                              void* d_out, int out_size) {
    const int* prefix = nullptr;
    const float *ctx = nullptr, *tables = nullptr, *lora = nullptr;
    const float *w1 = nullptr, *b1 = nullptr, *w2 = nullptr, *b2 = nullptr;
    for (int i = 0; i < n_in; i++) {
        switch (in_sizes[i]) {
            case 256:     prefix = (const int*)d_in[i];   break;  // (B,V) int32
            case 8388608: ctx    = (const float*)d_in[i]; break;  // (B,S,D)
            case 524288:  tables = (const float*)d_in[i]; break;  // (P,V,D)
            case 8192:    lora   = (const float*)d_in[i]; break;  // (P,D)
            case 43008:   w1     = (const float*)d_in[i]; break;  // (D,H)
            case 42:      b1     = (const float*)d_in[i]; break;  // (H,)
            case 2064384: w2     = (const float*)d_in[i]; break;  // (H,K)
            case 49152:   b2     = (const float*)d_in[i]; break;  // (K,)
        }
    }
    float* out = (float*)d_out;

    const int kavd_smem = (PP * SS + 32 * PP * 32) * 4;          // 98304 B
    cudaFuncSetAttribute(kavd, cudaFuncAttributeMaxDynamicSharedMemorySize, kavd_smem);
    const int kout_smem = (64 * AST2 + KT * BST2) * 2;           // 58624 B
    cudaFuncSetAttribute(kout, cudaFuncAttributeMaxDynamicSharedMemorySize, kout_smem);

    knorm<<<1024, 256>>>(ctx, lora, w1);
    ksofth<<<96, 256>>>(tables, b1);
    kavd<<<128, 1024, kavd_smem>>>(ctx, lora);
    kout<<<dim3(384, 4), 256, kout_smem>>>(prefix, w2, b2, out);   // profiled launch
}

// round 17
// speedup vs baseline: 1.0059x; 1.0059x over previous
#include <cuda_runtime.h>
#include <cuda_bf16.h>
#include <math.h>
#include <string.h>
#include <stdint.h>

#define BB 4
#define SS 2048
#define VV 64
#define DD 1024
#define PP 8
#define HH 42
#define KK 49152
#define EPSF 1e-12f
#define COSEPS 1e-8f
#define SQRT_S 45.254834f   // sqrt(2048)

typedef unsigned long long ull;

// ---------------- scratch (static device globals; no allocs allowed) ----------------
__device__ float g_w1t[HH * DD];              // w1 transposed [H][D]
__device__ float g_n[PP * BB * SS];           // n values
__device__ float g_wsm[PP * BB * SS];         // softmax weights over s
__device__ float4 g_cred[PP * BB * 32];       // cos partials {dot, an2, en2, 0} per (pb, dchunk)
__device__ float g_htab[PP * VV * HH];        // tanh(tables@w1+b1) [512][42]

// ---------------- kernel 1: knorm — n[p,b,s]; tail: w1 transpose ----------------
__global__ __launch_bounds__(256) void knorm(const float* __restrict__ ctx,
                                             const float* __restrict__ lora,
                                             const float* __restrict__ w1) {
    __shared__ float su[PP * DD];
    int t = threadIdx.x, warp = t >> 5, lane = t & 31;
    for (int i = t; i < PP * DD; i += 256) {
        float e = lora[i];
        su[i] = e / fmaxf(2.0f * fabsf(e), EPSF);
    }
    __syncthreads();
    int row = blockIdx.x * 8 + warp;
    int b = row >> 11, s = row & 2047;
    const float4* x4 = reinterpret_cast<const float4*>(ctx + (size_t)row * DD);
    float nrm2 = 0.f;
    float dot[PP];
#pragma unroll
    for (int p = 0; p < PP; p++) dot[p] = 0.f;
#pragma unroll
    for (int it = 0; it < 8; it++) {
        int q = lane + it * 32;
        float4 x = x4[q];
        nrm2 += x.x * x.x + x.y * x.y + x.z * x.z + x.w * x.w;
#pragma unroll
        for (int p = 0; p < PP; p++) {
            float4 u = reinterpret_cast<const float4*>(su + p * DD)[q];
            dot[p] += x.x * u.x + x.y * u.y + x.z * u.z + x.w * u.w;
        }
    }
#pragma unroll
    for (int o = 16; o; o >>= 1) {
        nrm2 += __shfl_xor_sync(0xffffffffu, nrm2, o);
#pragma unroll
        for (int p = 0; p < PP; p++) dot[p] += __shfl_xor_sync(0xffffffffu, dot[p], o);
    }
    if (lane < PP) {
        float dl = 0.f;
#pragma unroll
        for (int p = 0; p < PP; p++) if (lane == p) dl = dot[p];
        float v = dl / fmaxf(sqrtf(nrm2), EPSF);
        float c = fmaxf(v, 0.f);
        g_n[((size_t)lane * BB + b) * SS + s] = c / fmaxf(SQRT_S * c, EPSF);
    }
    if (blockIdx.x < 168) {
        int idx = blockIdx.x * 256 + t;
        int d = idx / HH, h = idx - d * HH;
        g_w1t[(size_t)h * DD + d] = w1[idx];
    }
}

// ---------------- kernel 2: ksofth — softmax (blk<32) || htab 8 rows (32<=blk<96) ----
__global__ __launch_bounds__(256) void ksofth(const float* __restrict__ tables,
                                              const float* __restrict__ b1) {
    __shared__ float smem[8 * DD];
    int blk = blockIdx.x;
    int t = threadIdx.x, warp = t >> 5, lane = t & 31;
    if (blk < 32) {
        float* sn = smem;
        float* red = smem + SS;
        int pb = blk;
        const float* np = g_n + (size_t)pb * SS;
        float m = -1e30f;
        for (int i = t; i < SS; i += 256) { float v = np[i]; sn[i] = v; m = fmaxf(m, v); }
        red[t] = m; __syncthreads();
        for (int o = 128; o; o >>= 1) { if (t < o) red[t] = fmaxf(red[t], red[t + o]); __syncthreads(); }
        m = red[0]; __syncthreads();
        float sum = 0.f;
        for (int i = t; i < SS; i += 256) sum += expf(sn[i] - m);
        red[t] = sum; __syncthreads();
        for (int o = 128; o; o >>= 1) { if (t < o) red[t] += red[t + o]; __syncthreads(); }
        float inv = 1.0f / red[0];
        for (int i = t; i < SS; i += 256) g_wsm[(size_t)pb * SS + i] = expf(sn[i] - m) * inv;
    } else {
        float* tok = smem;
        int oct = blk - 32;
        const float* src = tables + (size_t)oct * 8 * DD;
        for (int i = t; i < 8 * DD; i += 256) tok[i] = src[i];
        __syncthreads();
#pragma unroll
        for (int j = 0; j < 6; j++) {
            int h = warp + j * 8;
            if (h < HH) {
                const float4* wr = reinterpret_cast<const float4*>(g_w1t + (size_t)h * DD);
                float dt[8];
#pragma unroll
                for (int r = 0; r < 8; r++) dt[r] = 0.f;
#pragma unroll
                for (int it = 0; it < 8; it++) {
                    int q = lane + it * 32;
                    float4 wv = wr[q];
#pragma unroll
                    for (int r = 0; r < 8; r++) {
                        float4 tv = reinterpret_cast<const float4*>(tok + r * DD)[q];
                        dt[r] += wv.x * tv.x + wv.y * tv.y + wv.z * tv.z + wv.w * tv.w;
                    }
                }
#pragma unroll
                for (int o = 16; o; o >>= 1)
#pragma unroll
                    for (int r = 0; r < 8; r++) dt[r] += __shfl_xor_sync(0xffffffffu, dt[r], o);
                if (lane < 8) {
                    float dl = 0.f;
#pragma unroll
                    for (int r = 0; r < 8; r++) if (lane == r) dl = dt[r];
                    g_htab[(size_t)(oct * 8 + lane) * HH + h] = tanhf(dl + b1[h]);
                }
            }
        }
    }
}

// ---------------- kernel 3: kavd — direct a_v + cos partials ----------------
__global__ __launch_bounds__(1024) void kavd(const float* __restrict__ ctx,
                                             const float* __restrict__ lora) {
    extern __shared__ float dsm[];
    float* ws = dsm;
    float* red = dsm + PP * SS;
    int b = blockIdx.x & 3, dchunk = blockIdx.x >> 2;
    int t = threadIdx.x, w = t >> 5, lane = t & 31;
    for (int i = t; i < PP * SS; i += 1024) {
        int p = i >> 11, s = i & 2047;
        ws[i] = g_wsm[((size_t)p * BB + b) * SS + s];
    }
    __syncthreads();
    int d = dchunk * 32 + lane;
    const float* cb = ctx + (size_t)b * SS * DD + d;
    int s0 = w * 64;
    float acc[PP];
#pragma unroll
    for (int p = 0; p < PP; p++) acc[p] = 0.f;
#pragma unroll
    for (int sb = 0; sb < 64; sb += 16) {
        float x[16];
#pragma unroll
        for (int r = 0; r < 16; r++) x[r] = cb[(size_t)(s0 + sb + r) * DD];
#pragma unroll
        for (int r = 0; r < 16; r++) {
            int s = s0 + sb + r;
            float xs = x[r];
#pragma unroll
            for (int p = 0; p < PP; p++) acc[p] += ws[p * SS + s] * xs;
        }
    }
#pragma unroll
    for (int p = 0; p < PP; p++) red[(w * PP + p) * 32 + lane] = acc[p];
    __syncthreads();
    if (w < PP) {
        int p = w;
        float av = 0.f;
#pragma unroll
        for (int ww = 0; ww < 32; ww++) av += red[(ww * PP + p) * 32 + lane];
        float e = lora[(size_t)p * DD + d];
        float dotv = e * av, an2 = av * av, en2 = e * e;
#pragma unroll
        for (int o = 16; o; o >>= 1) {
            dotv += __shfl_xor_sync(0xffffffffu, dotv, o);
            an2  += __shfl_xor_sync(0xffffffffu, an2, o);
            en2  += __shfl_xor_sync(0xffffffffu, en2, o);
        }
        if (lane == 0)
            g_cred[(p * BB + b) * 32 + dchunk] = make_float4(dotv, an2, en2, 0.f);
    }
}

// ---------------- kernel 4: kout — split-bf16 HMMA GEMM ----------------
// out[256,49152] = hbar[256,42] @ w2 + b2 with A' = [Ah|Ah|Al] (K=144),
// B' = [Wh;Wl;Wh] so one MMA chain = AhWh + AhWl + AlWh (err ~2^-18).
// Block: 256 thr = 8 warps (4 m16 x 2 n64). Tile M=64 x N=128. grid (384,4).

#define KSEG 48                 // padded K per segment (42 -> 48)
#define KT 144                  // 3 segments
#define AST2 152                // A smem row stride (bf16) -> 304B, 16B-mult, conflict-free
#define BST2 136                // B smem row stride (bf16) -> 272B, 16B-mult, conflict-free

__device__ __forceinline__ uint32_t smem_u32(const void* p) {
    return (uint32_t)__cvta_generic_to_shared(p);
}

#define LDSM_X4(r0,r1,r2,r3,addr) \
    asm volatile("ldmatrix.sync.aligned.m8n8.x4.shared.b16 {%0,%1,%2,%3}, [%4];" \
        : "=r"(r0), "=r"(r1), "=r"(r2), "=r"(r3) : "r"(addr))

#define LDSM_X4T(r0,r1,r2,r3,addr) \
    asm volatile("ldmatrix.sync.aligned.m8n8.x4.trans.shared.b16 {%0,%1,%2,%3}, [%4];" \
        : "=r"(r0), "=r"(r1), "=r"(r2), "=r"(r3) : "r"(addr))

#define MMA_BF16(d, a0,a1,a2,a3, b0,b1) \
    asm volatile("mma.sync.aligned.m16n8k16.row.col.f32.bf16.bf16.f32 " \
        "{%0,%1,%2,%3}, {%4,%5,%6,%7}, {%8,%9}, {%0,%1,%2,%3};" \
        : "+f"(d[0]), "+f"(d[1]), "+f"(d[2]), "+f"(d[3]) \
        : "r"(a0), "r"(a1), "r"(a2), "r"(a3), "r"(b0), "r"(b1))

__global__ __launch_bounds__(256) void kout(const int* __restrict__ prefix,
                                            const float* __restrict__ w2,
                                            const float* __restrict__ b2,
                                            float* __restrict__ out) {
    extern __shared__ __nv_bfloat16 bsm[];
    __nv_bfloat16* s_a = bsm;                   // [64][AST2]
    __nv_bfloat16* s_b = bsm + 64 * AST2;       // [KT][BST2]
    __shared__ float scos[32];
    __shared__ float sgate[32];

    int t = threadIdx.x;
    int r0g = blockIdx.y * 64;
    int col0 = blockIdx.x * 128;

    // ---- gates (t<32) ----
    if (t < 32) {
        float D = 0.f, A = 0.f, E = 0.f;
#pragma unroll 8
        for (int c = 0; c < 32; c++) {
            float4 f = g_cred[t * 32 + c];
            D += f.x; A += f.y; E += f.z;
        }
        scos[t] = D / fmaxf(sqrtf(E) * sqrtf(A), COSEPS);
        __syncwarp();
        int bq = t >> 3, p = t & 7;
        float x[PP], m = -1e30f;
#pragma unroll
        for (int pp = 0; pp < PP; pp++) { x[pp] = scos[pp * BB + bq]; m = fmaxf(m, x[pp]); }
        float z = 0.f;
#pragma unroll
        for (int pp = 0; pp < PP; pp++) { x[pp] = expf(x[pp] - m); z += x[pp]; }
#pragma unroll
        for (int pp = 0; pp < PP; pp++) x[pp] /= z;
        m = -1e30f;
#pragma unroll
        for (int pp = 0; pp < PP; pp++) m = fmaxf(m, x[pp]);
        z = 0.f;
#pragma unroll
        for (int pp = 0; pp < PP; pp++) { x[pp] = expf(x[pp] - m); z += x[pp]; }
        sgate[t] = x[p] / z;
    }
    __syncthreads();

    // ---- stage A' = [Ah | Ah | Al] per row (hbar gather + split) ----
    for (int i = t; i < 64 * KSEG; i += 256) {
        int r = i / KSEG, h = i - r * KSEG;
        float v = 0.f;
        if (h < HH) {
            int bv = r0g + r;
            int pf = prefix[bv];
            int bq = bv >> 6;
            float s = 0.f;
#pragma unroll
            for (int p = 0; p < PP; p++)
                s += sgate[bq * 8 + p] * g_htab[((size_t)p * VV + pf) * HH + h];
            v = s;
        }
        __nv_bfloat16 ah = __float2bfloat16(v);
        __nv_bfloat16 al = __float2bfloat16(v - __bfloat162float(ah));
        s_a[r * AST2 + h]            = ah;
        s_a[r * AST2 + KSEG + h]     = ah;
        s_a[r * AST2 + 2 * KSEG + h] = al;
    }
    // ---- stage B' = [Wh ; Wl ; Wh] ----
    for (int i = t; i < KSEG * 128; i += 256) {
        int k = i >> 7, n = i & 127;
        float v = (k < HH) ? w2[(size_t)k * KK + col0 + n] : 0.f;
        __nv_bfloat16 wh = __float2bfloat16(v);
        __nv_bfloat16 wl = __float2bfloat16(v - __bfloat162float(wh));
        s_b[k * BST2 + n]                = wh;
        s_b[(KSEG + k) * BST2 + n]       = wl;
        s_b[(2 * KSEG + k) * BST2 + n]   = wh;
    }
    __syncthreads();

    // ---- MMA mainloop: 9 k16 chunks ----
    int w = t >> 5, lane = t & 31;
    int mi = w & 3, ni = w >> 2;               // 4 m16 tiles x 2 n64 halves
    int lmat = lane >> 3, lrow = lane & 7;

    uint32_t a_base = smem_u32(s_a) +
        (((mi * 16 + (lmat & 1) * 8 + lrow) * AST2) + (lmat >> 1) * 8) * 2;
    uint32_t b_base = smem_u32(s_b) +
        ((((lmat & 1) * 8 + lrow) * BST2) + ni * 64 + (lmat >> 1) * 8) * 2;

    float acc[8][4];
#pragma unroll
    for (int j = 0; j < 8; j++)
#pragma unroll
        for (int q = 0; q < 4; q++) acc[j][q] = 0.f;

#pragma unroll
    for (int kc = 0; kc < 9; kc++) {
        uint32_t a0, a1, a2, a3;
        LDSM_X4(a0, a1, a2, a3, a_base + kc * 16 * 2);
#pragma unroll
        for (int j = 0; j < 4; j++) {
            uint32_t b0, b1, b2v, b3;
            LDSM_X4T(b0, b1, b2v, b3, b_base + (kc * 16 * BST2 + j * 16) * 2);
            MMA_BF16(acc[2 * j],     a0, a1, a2, a3, b0, b1);
            MMA_BF16(acc[2 * j + 1], a0, a1, a2, a3, b2v, b3);
        }
    }

    // ---- store with bias ----
    int row = r0g + mi * 16 + (lane >> 2);
#pragma unroll
    for (int j = 0; j < 8; j++) {
        int col = col0 + ni * 64 + j * 8 + (lane & 3) * 2;
        float2 bb = *reinterpret_cast<const float2*>(b2 + col);
        float2 o0 = make_float2(acc[j][0] + bb.x, acc[j][1] + bb.y);
        float2 o1 = make_float2(acc[j][2] + bb.x, acc[j][3] + bb.y);
        *reinterpret_cast<float2*>(out + (size_t)row * KK + col) = o0;
        *reinterpret_cast<float2*>(out + (size_t)(row + 8) * KK + col) = o1;
    }
}

// ---------------- launcher ----------------
extern "C" void kernel_launch(void* const* d_in, const int* in_sizes, int n_in,
                              void* d_out, int out_size) {
    const int* prefix = nullptr;
    const float *ctx = nullptr, *tables = nullptr, *lora = nullptr;
    const float *w1 = nullptr, *b1 = nullptr, *w2 = nullptr, *b2 = nullptr;
    for (int i = 0; i < n_in; i++) {
        switch (in_sizes[i]) {
            case 256:     prefix = (const int*)d_in[i];   break;  // (B,V) int32
            case 8388608: ctx    = (const float*)d_in[i]; break;  // (B,S,D)
            case 524288:  tables = (const float*)d_in[i]; break;  // (P,V,D)
            case 8192:    lora   = (const float*)d_in[i]; break;  // (P,D)
            case 43008:   w1     = (const float*)d_in[i]; break;  // (D,H)
            case 42:      b1     = (const float*)d_in[i]; break;  // (H,)
            case 2064384: w2     = (const float*)d_in[i]; break;  // (H,K)
            case 49152:   b2     = (const float*)d_in[i]; break;  // (K,)
        }
    }
    float* out = (float*)d_out;

    const int kavd_smem = (PP * SS + 32 * PP * 32) * 4;          // 98304 B
    cudaFuncSetAttribute(kavd, cudaFuncAttributeMaxDynamicSharedMemorySize, kavd_smem);
    const int kout_smem = (64 * AST2 + KT * BST2) * 2;           // 58624 B
    cudaFuncSetAttribute(kout, cudaFuncAttributeMaxDynamicSharedMemorySize, kout_smem);

    knorm<<<1024, 256>>>(ctx, lora, w1);
    ksofth<<<96, 256>>>(tables, b1);
    kavd<<<128, 1024, kavd_smem>>>(ctx, lora);
    kout<<<dim3(384, 4), 256, kout_smem>>>(prefix, w2, b2, out);   // profiled launch
}